// round 5
// baseline (speedup 1.0000x reference)
#include <cuda_runtime.h>
#include <cstdint>
#include <cstddef>

#define Bsz 128
#define Ssz 1024
#define Dsz 256
#define Hsz 256
#define G3  768

// 402 MB scratch for precomputed input gates gx = x @ W_ih + b_ih
__device__ float g_gx[(size_t)Bsz * Ssz * G3];

typedef unsigned long long ull;

__device__ __forceinline__ ull pack2(float a) {
    ull r;
    asm("mov.b64 %0, {%1, %1};" : "=l"(r) : "f"(a));
    return r;
}
__device__ __forceinline__ ull pk(float a, float b) {
    ull r;
    asm("mov.b64 %0, {%1, %2};" : "=l"(r) : "f"(a), "f"(b));
    return r;
}
__device__ __forceinline__ void fma2(ull& acc, ull a, ull b) {
    asm("fma.rn.f32x2 %0, %1, %2, %0;" : "+l"(acc) : "l"(a), "l"(b));
}
__device__ __forceinline__ ull add2(ull a, ull b) {
    ull r;
    asm("add.rn.f32x2 %0, %1, %2;" : "=l"(r) : "l"(a), "l"(b));
    return r;
}
__device__ __forceinline__ float2 unpack2(ull v) {
    float2 f;
    asm("mov.b64 {%0, %1}, %2;" : "=f"(f.x), "=f"(f.y) : "l"(v));
    return f;
}

// ---------------------------------------------------------------------------
// Kernel A: gx[M=131072, 768] = X[M,256] @ W_ih[256,768] + b_ih
// (unchanged from round 4 — ~1.1 ms)
// ---------------------------------------------------------------------------
__global__ __launch_bounds__(256) void gemm_gx_kernel(
    const float* __restrict__ X, const float* __restrict__ W,
    const float* __restrict__ bias)
{
    __shared__ float As[16][128];
    __shared__ float Bs[16][128];

    const int tid  = threadIdx.x;
    const int brow = blockIdx.y * 128;
    const int bcol = blockIdx.x * 128;
    const int ty   = tid >> 4;
    const int tx   = tid & 15;

    ull acc2[8][4];
#pragma unroll
    for (int i = 0; i < 8; i++)
#pragma unroll
        for (int j = 0; j < 4; j++) acc2[i][j] = 0ull;

    float4 pa[2], pb[2];
    int aoff[2], boff[2], akk[2];
#pragma unroll
    for (int it = 0; it < 2; it++) {
        int id = tid + it * 256;
        aoff[it] = id >> 2;
        akk[it]  = (id & 3) << 2;
        boff[it] = id;
    }
#pragma unroll
    for (int it = 0; it < 2; it++) {
        pa[it] = *reinterpret_cast<const float4*>(
            &X[(size_t)(brow + aoff[it]) * Dsz + akk[it]]);
        pb[it] = *reinterpret_cast<const float4*>(
            &W[(size_t)(boff[it] >> 5) * G3 + bcol + ((boff[it] & 31) << 2)]);
    }

    for (int k0 = 0; k0 < Dsz; k0 += 16) {
#pragma unroll
        for (int it = 0; it < 2; it++) {
            As[akk[it] + 0][aoff[it]] = pa[it].x;
            As[akk[it] + 1][aoff[it]] = pa[it].y;
            As[akk[it] + 2][aoff[it]] = pa[it].z;
            As[akk[it] + 3][aoff[it]] = pa[it].w;
            *reinterpret_cast<float4*>(&Bs[boff[it] >> 5][(boff[it] & 31) << 2]) = pb[it];
        }
        __syncthreads();

        if (k0 + 16 < Dsz) {
#pragma unroll
            for (int it = 0; it < 2; it++) {
                pa[it] = *reinterpret_cast<const float4*>(
                    &X[(size_t)(brow + aoff[it]) * Dsz + (k0 + 16) + akk[it]]);
                pb[it] = *reinterpret_cast<const float4*>(
                    &W[(size_t)((k0 + 16) + (boff[it] >> 5)) * G3 + bcol + ((boff[it] & 31) << 2)]);
            }
        }

#pragma unroll
        for (int kk = 0; kk < 16; kk++) {
            float ra[8];
            ull   rb2[4];
            *reinterpret_cast<float4*>(&ra[0]) = *reinterpret_cast<float4*>(&As[kk][ty * 8]);
            *reinterpret_cast<float4*>(&ra[4]) = *reinterpret_cast<float4*>(&As[kk][ty * 8 + 4]);
            ulonglong2 b01 = *reinterpret_cast<ulonglong2*>(&Bs[kk][tx * 8]);
            ulonglong2 b23 = *reinterpret_cast<ulonglong2*>(&Bs[kk][tx * 8 + 4]);
            rb2[0] = b01.x; rb2[1] = b01.y; rb2[2] = b23.x; rb2[3] = b23.y;
#pragma unroll
            for (int i = 0; i < 8; i++) {
                ull ra2 = pack2(ra[i]);
#pragma unroll
                for (int j = 0; j < 4; j++)
                    fma2(acc2[i][j], ra2, rb2[j]);
            }
        }
        __syncthreads();
    }

#pragma unroll
    for (int i = 0; i < 8; i++) {
        int row = brow + ty * 8 + i;
#pragma unroll
        for (int j2 = 0; j2 < 2; j2++) {
            int col = bcol + tx * 8 + j2 * 4;
            float4 bv = *reinterpret_cast<const float4*>(&bias[col]);
            float2 c0 = unpack2(acc2[i][j2 * 2 + 0]);
            float2 c1 = unpack2(acc2[i][j2 * 2 + 1]);
            float4 cv;
            cv.x = c0.x + bv.x;
            cv.y = c0.y + bv.y;
            cv.z = c1.x + bv.z;
            cv.w = c1.y + bv.w;
            *reinterpret_cast<float4*>(&g_gx[(size_t)row * G3 + col]) = cv;
        }
    }
}

// ---------------------------------------------------------------------------
// Kernel B: persistent GRU recurrence — pack-free FFMA2 GEMM.
// Cluster of 4 CTAs per 4 batch rows; CTA rank r owns j in [64r, 64r+64).
// Thread (warp kq=0..15, lane jp=0..31): j-pair (2jp, 2jp+1), k-chunk 16.
// Accumulators: (r,z) gate-pairs per (j,b) + (n_j0,n_j1) pairs per b.
// Weights: 12 k in registers (pre-packed pairs of DISTINCT scalars),
// 4 k in smem as pairs (LDS.64, no pack at use).
// h is stored DUPLICATED (h,h) in smem (scatter writes st.async.b64),
// so GEMM does 0 mov-packs per step.
// Sync: st.async + tx-counted ping-pong mbarriers (round-4 protocol).
// ---------------------------------------------------------------------------
#define TPB_B 512

// smem in ull units: Ws2[64][96] | hb2[2][256][4] | redU[16][4][96]
#define ULL_W   0
#define ULL_H   (64 * 96)                 // 6144
#define ULL_RED (ULL_H + 2 * 256 * 4)     // 8192
#define ULL_TOT (ULL_RED + 16 * 4 * 96)   // 14336
#define SMEM_B_BYTES (ULL_TOT * 8 + 16)

__device__ __forceinline__ float sigmoidf_fast(float x) {
    return __fdividef(1.0f, 1.0f + __expf(-x));
}
__device__ __forceinline__ float tanhf_fast(float x) {
    x = fminf(fmaxf(x, -15.f), 15.f);
    float e = __expf(2.f * x);
    return __fdividef(e - 1.f, e + 1.f);
}

__device__ __forceinline__ void mbar_wait_parity(uint32_t mbar, uint32_t parity) {
    asm volatile(
        "{\n\t"
        ".reg .pred P;\n\t"
        "WAIT_%=:\n\t"
        "mbarrier.try_wait.parity.acquire.cluster.shared::cta.b64 P, [%0], %1, 0x989680;\n\t"
        "@P bra DONE_%=;\n\t"
        "bra WAIT_%=;\n\t"
        "DONE_%=:\n\t"
        "}"
        :: "r"(mbar), "r"(parity) : "memory");
}

__global__ void __cluster_dims__(4, 1, 1) __launch_bounds__(TPB_B, 1)
gru_rec_kernel(const float* __restrict__ mask,
               const float* __restrict__ Whh,
               const float* __restrict__ bhh,
               float* __restrict__ out)
{
    extern __shared__ ull smu[];
    ull* Ws2  = smu + ULL_W;    // [64][96]: 96 = {rz_j0:32 | rz_j1:32 | n:32}
    ull* hb2  = smu + ULL_H;    // [2][256][4] duplicated h pairs
    ull* redU = smu + ULL_RED;  // [16][4][96]

    const int tid = threadIdx.x;
    uint32_t rank;
    asm("mov.u32 %0, %%cluster_ctarank;" : "=r"(rank));
    const int ci = (int)blockIdx.x >> 2;

    uint32_t sm_u32;
    asm("{ .reg .u64 t; cvta.to.shared.u64 t, %1; cvt.u32.u64 %0, t; }"
        : "=r"(sm_u32) : "l"(smu));
    const uint32_t hb_u32   = sm_u32 + ULL_H * 8;
    const uint32_t mbar_u32 = sm_u32 + ULL_TOT * 8;

    // tx-counted mbarriers: 1 arrival (thread0) + 8192B tx (1024 x 8B) per phase
    if (tid == 0) {
        asm volatile("mbarrier.init.shared.b64 [%0], 1;" :: "r"(mbar_u32) : "memory");
        asm volatile("mbarrier.init.shared.b64 [%0], 1;" :: "r"(mbar_u32 + 8) : "memory");
        asm volatile("mbarrier.arrive.expect_tx.shared.b64 _, [%0], 8192;"
                     :: "r"(mbar_u32) : "memory");
        asm volatile("mbarrier.arrive.expect_tx.shared.b64 _, [%0], 8192;"
                     :: "r"(mbar_u32 + 8) : "memory");
    }

    // Stage smem weights: k with (k & 15) >= 12. kk_glob = (k>>4)*4 + (k&3).
    for (int idx = tid; idx < 64 * 96; idx += TPB_B) {
        int kkg = idx / 96;
        int r2  = idx - kkg * 96;
        int g   = r2 >> 5;        // 0: rz_j0, 1: rz_j1, 2: n-pair
        int jp  = r2 & 31;
        int k   = (kkg >> 2) * 16 + 12 + (kkg & 3);
        int j0  = (int)rank * 64 + jp * 2;
        float a, b;
        if (g == 0)      { a = Whh[k * G3 + j0];       b = Whh[k * G3 + 256 + j0]; }
        else if (g == 1) { a = Whh[k * G3 + j0 + 1];   b = Whh[k * G3 + 256 + j0 + 1]; }
        else             { a = Whh[k * G3 + 512 + j0]; b = Whh[k * G3 + 512 + j0 + 1]; }
        Ws2[idx] = pk(a, b);
    }
    // Zero h buffer parity 0 (h0 = 0)
    for (int idx = tid; idx < 2 * 256 * 4; idx += TPB_B) hb2[idx] = 0ull;

    const int kq = tid >> 5;          // warp id: k-chunk
    const int jp = tid & 31;          // lane: j-pair
    const int k0 = kq * 16;
    const int jg0 = (int)rank * 64 + jp * 2;

    // Register weights: k in [k0, k0+12), pairs of distinct scalars
    ull wrz0[12], wrz1[12], wn[12];
#pragma unroll
    for (int kk = 0; kk < 12; kk++) {
        int k = k0 + kk;
        wrz0[kk] = pk(Whh[k * G3 + jg0],       Whh[k * G3 + 256 + jg0]);
        wrz1[kk] = pk(Whh[k * G3 + jg0 + 1],   Whh[k * G3 + 256 + jg0 + 1]);
        wn[kk]   = pk(Whh[k * G3 + 512 + jg0], Whh[k * G3 + 512 + jg0 + 1]);
    }

    // Elementwise threads: tid < 256: j = tid&63, b = tid>>6
    const bool ew = (tid < 256);
    const int je = tid & 63;
    const int be = tid >> 6;
    const int jge = (int)rank * 64 + je;
    float bhr = 0.f, bhz = 0.f, bhn = 0.f;
    const float* gx_p = nullptr;
    const float* m_p  = nullptr;
    float* out_p = nullptr;
    if (ew) {
        bhr = bhh[jge];
        bhz = bhh[256 + jge];
        bhn = bhh[512 + jge];
        int bbg = ci * 4 + be;
        gx_p  = g_gx + (size_t)bbg * Ssz * G3;
        m_p   = mask + (size_t)bbg * Ssz;
        out_p = out + (size_t)bbg * Ssz * Hsz + jge;
    }

    __syncthreads();
    asm volatile("barrier.cluster.arrive.aligned;" ::: "memory");
    asm volatile("barrier.cluster.wait.aligned;" ::: "memory");

    int ph0 = 0, ph1 = 0;

    for (int t = 0; t < Ssz; t++) {
        // gx/mask prefetch before the wait (no h dependency)
        float gxr = 0.f, gxz = 0.f, gxn = 0.f, mt = 0.f;
        if (ew) {
            const float* gxt = gx_p + (size_t)t * G3;
            gxr = __ldcs(gxt + jge);
            gxz = __ldcs(gxt + 256 + jge);
            gxn = __ldcs(gxt + 512 + jge);
            mt  = __ldg(m_p + t);
        }

        const int mi = t & 1;
        if (t > 0) {
            uint32_t mb = mbar_u32 + (uint32_t)(mi * 8);
            if (mi == 0) { mbar_wait_parity(mb, ph0); ph0 ^= 1; }
            else         { mbar_wait_parity(mb, ph1); ph1 ^= 1; }
            if (tid == 0 && t + 2 < Ssz)
                asm volatile("mbarrier.arrive.expect_tx.shared.b64 _, [%0], 8192;"
                             :: "r"(mb) : "memory");
        }

        float hold = 0.f;
        if (ew)
            hold = *reinterpret_cast<const float*>(&hb2[mi * 1024 + jge * 4 + be]);

        // ---- gh GEMM: pack-free FFMA2 ----
        ull a_rz0[4] = {0, 0, 0, 0};   // (r,z) for j0, per batch
        ull a_rz1[4] = {0, 0, 0, 0};   // (r,z) for j1
        ull a_n[4]   = {0, 0, 0, 0};   // (n_j0, n_j1)
        const ull* hK = hb2 + mi * 1024 + k0 * 4;

        // k offsets 0..11: register weights
#pragma unroll
        for (int kk = 0; kk < 12; kk++) {
            ulonglong2 h01 = *reinterpret_cast<const ulonglong2*>(hK + kk * 4);
            ulonglong2 h23 = *reinterpret_cast<const ulonglong2*>(hK + kk * 4 + 2);
            ull hh[4] = {h01.x, h01.y, h23.x, h23.y};
#pragma unroll
            for (int b = 0; b < 4; b++) {
                fma2(a_rz0[b], hh[b], wrz0[kk]);
                fma2(a_rz1[b], hh[b], wrz1[kk]);
                fma2(a_n[b],   hh[b], wn[kk]);
            }
        }
        // k offsets 12..15: smem weights (LDS.64, no pack)
#pragma unroll
        for (int kk = 0; kk < 4; kk++) {
            const ull* wb = Ws2 + (kq * 4 + kk) * 96;
            ull w0 = wb[jp];
            ull w1 = wb[32 + jp];
            ull w2 = wb[64 + jp];
            ulonglong2 h01 = *reinterpret_cast<const ulonglong2*>(hK + (12 + kk) * 4);
            ulonglong2 h23 = *reinterpret_cast<const ulonglong2*>(hK + (12 + kk) * 4 + 2);
            ull hh[4] = {h01.x, h01.y, h23.x, h23.y};
#pragma unroll
            for (int b = 0; b < 4; b++) {
                fma2(a_rz0[b], hh[b], w0);
                fma2(a_rz1[b], hh[b], w1);
                fma2(a_n[b],   hh[b], w2);
            }
        }

        // partials -> redU[kq][b][{jp | 32+jp | 64+jp}]
        {
            ull* rb = redU + kq * 384;
#pragma unroll
            for (int b = 0; b < 4; b++) {
                rb[b * 96 + jp]      = a_rz0[b];
                rb[b * 96 + 32 + jp] = a_rz1[b];
                rb[b * 96 + 64 + jp] = a_n[b];
            }
        }
        __syncthreads();

        if (ew) {
            // reduce 16 kq partials
            ull rz = pk(bhr, bhz);
            float nsum = bhn;
            const int rzoff = be * 96 + ((je & 1) << 5) + (je >> 1);
            const int noff  = be * 96 + 64 + (je >> 1);
            const int nlane = je & 1;
#pragma unroll
            for (int q = 0; q < 16; q++) {
                rz = add2(rz, redU[q * 384 + rzoff]);
                nsum += reinterpret_cast<const float*>(redU + q * 384 + noff)[nlane];
            }
            float2 rzf = unpack2(rz);
            float r = sigmoidf_fast(gxr + rzf.x);
            float z = sigmoidf_fast(gxz + rzf.y);
            float n = tanhf_fast(fmaf(r, nsum, gxn));
            float hnew = fmaf(z, hold - n, n);           // (1-z)*n + z*hold
            float hout = fmaf(mt, hnew - hold, hold);    // m*hnew + (1-m)*hold
            out_p[(size_t)t * Hsz] = hout;

            if (t < Ssz - 1) {
                // async duplicated store into hb2[(t+1)&1] of all 4 CTAs
                ull hd = pk(hout, hout);
                uint32_t laddr = hb_u32 +
                    (uint32_t)(((((t + 1) & 1) * 1024) + jge * 4 + be) * 8);
                uint32_t lmb = mbar_u32 + (uint32_t)(((t + 1) & 1) * 8);
#pragma unroll
                for (int pp = 0; pp < 4; pp++) {
                    uint32_t raddr, rmb;
                    asm volatile("mapa.shared::cluster.u32 %0, %1, %2;"
                                 : "=r"(raddr) : "r"(laddr), "r"(pp));
                    asm volatile("mapa.shared::cluster.u32 %0, %1, %2;"
                                 : "=r"(rmb) : "r"(lmb), "r"(pp));
                    asm volatile(
                        "st.async.shared::cluster.mbarrier::complete_tx::bytes.b64 "
                        "[%0], %1, [%2];"
                        :: "r"(raddr), "l"(hd), "r"(rmb) : "memory");
                }
            }
        }
    }
}

// ---------------------------------------------------------------------------
extern "C" void kernel_launch(void* const* d_in, const int* in_sizes, int n_in,
                              void* d_out, int out_size)
{
    (void)in_sizes; (void)n_in; (void)out_size;
    const float* x    = (const float*)d_in[0];
    const float* mask = (const float*)d_in[1];
    const float* Wih  = (const float*)d_in[2];
    const float* Whh  = (const float*)d_in[3];
    const float* bih  = (const float*)d_in[4];
    const float* bhh  = (const float*)d_in[5];
    float* out = (float*)d_out;

    cudaFuncSetAttribute(gru_rec_kernel,
                         cudaFuncAttributeMaxDynamicSharedMemorySize,
                         SMEM_B_BYTES);

    dim3 gridA(G3 / 128, (Bsz * Ssz) / 128);
    gemm_gx_kernel<<<gridA, 256>>>(x, Wih, bih);

    gru_rec_kernel<<<Bsz, TPB_B, SMEM_B_BYTES>>>(mask, Whh, bhh, out);
}

// round 6
// speedup vs baseline: 1.0668x; 1.0668x over previous
#include <cuda_runtime.h>
#include <cstdint>
#include <cstddef>

#define Bsz 128
#define Ssz 1024
#define Dsz 256
#define Hsz 256
#define G3  768

// 402 MB scratch for precomputed input gates gx = x @ W_ih + b_ih
__device__ float g_gx[(size_t)Bsz * Ssz * G3];

typedef unsigned long long ull;

__device__ __forceinline__ ull pack2(float a) {
    ull r;
    asm("mov.b64 %0, {%1, %1};" : "=l"(r) : "f"(a));
    return r;
}
__device__ __forceinline__ ull pk(float a, float b) {
    ull r;
    asm("mov.b64 %0, {%1, %2};" : "=l"(r) : "f"(a), "f"(b));
    return r;
}
__device__ __forceinline__ void fma2(ull& acc, ull a, ull b) {
    asm("fma.rn.f32x2 %0, %1, %2, %0;" : "+l"(acc) : "l"(a), "l"(b));
}
__device__ __forceinline__ float2 unpack2(ull v) {
    float2 f;
    asm("mov.b64 {%0, %1}, %2;" : "=f"(f.x), "=f"(f.y) : "l"(v));
    return f;
}

// ---------------------------------------------------------------------------
// Kernel A: gx[M=131072, 768] = X[M,256] @ W_ih[256,768] + b_ih
// 128x128 block tile, BK=32 (8 outer iters, 16 syncs), 256 threads,
// 8x8 microtile FFMA2, register-prefetched global loads, 2 CTAs/SM.
// ---------------------------------------------------------------------------
__global__ __launch_bounds__(256, 2) void gemm_gx_kernel(
    const float* __restrict__ X, const float* __restrict__ W,
    const float* __restrict__ bias)
{
    __shared__ float As[32][128];   // [k][row]
    __shared__ float Bs[32][128];   // [k][col]

    const int tid  = threadIdx.x;
    const int brow = blockIdx.y * 128;
    const int bcol = blockIdx.x * 128;
    const int ty   = tid >> 4;
    const int tx   = tid & 15;

    ull acc2[8][4];
#pragma unroll
    for (int i = 0; i < 8; i++)
#pragma unroll
        for (int j = 0; j < 4; j++) acc2[i][j] = 0ull;

    int aoff[4], akk[4], bkk[4], bcc[4];
#pragma unroll
    for (int it = 0; it < 4; it++) {
        int id = tid + it * 256;
        aoff[it] = id >> 3;            // A row 0..127
        akk[it]  = (id & 7) << 2;      // A k sub 0..28
        bkk[it]  = id >> 5;            // B k 0..31
        bcc[it]  = (id & 31) << 2;     // B col 0..124
    }

    float4 pa[4], pb[4];
#pragma unroll
    for (int it = 0; it < 4; it++) {
        pa[it] = *reinterpret_cast<const float4*>(
            &X[(size_t)(brow + aoff[it]) * Dsz + akk[it]]);
        pb[it] = *reinterpret_cast<const float4*>(
            &W[(size_t)bkk[it] * G3 + bcol + bcc[it]]);
    }

    for (int k0 = 0; k0 < Dsz; k0 += 32) {
        // commit prefetched tile to smem
#pragma unroll
        for (int it = 0; it < 4; it++) {
            As[akk[it] + 0][aoff[it]] = pa[it].x;
            As[akk[it] + 1][aoff[it]] = pa[it].y;
            As[akk[it] + 2][aoff[it]] = pa[it].z;
            As[akk[it] + 3][aoff[it]] = pa[it].w;
            *reinterpret_cast<float4*>(&Bs[bkk[it]][bcc[it]]) = pb[it];
        }
        __syncthreads();

        // issue next tile loads (overlap with compute)
        if (k0 + 32 < Dsz) {
#pragma unroll
            for (int it = 0; it < 4; it++) {
                pa[it] = *reinterpret_cast<const float4*>(
                    &X[(size_t)(brow + aoff[it]) * Dsz + (k0 + 32) + akk[it]]);
                pb[it] = *reinterpret_cast<const float4*>(
                    &W[(size_t)((k0 + 32) + bkk[it]) * G3 + bcol + bcc[it]]);
            }
        }

#pragma unroll 8
        for (int kk = 0; kk < 32; kk++) {
            float ra[8];
            ull   rb2[4];
            *reinterpret_cast<float4*>(&ra[0]) = *reinterpret_cast<float4*>(&As[kk][ty * 8]);
            *reinterpret_cast<float4*>(&ra[4]) = *reinterpret_cast<float4*>(&As[kk][ty * 8 + 4]);
            ulonglong2 b01 = *reinterpret_cast<ulonglong2*>(&Bs[kk][tx * 8]);
            ulonglong2 b23 = *reinterpret_cast<ulonglong2*>(&Bs[kk][tx * 8 + 4]);
            rb2[0] = b01.x; rb2[1] = b01.y; rb2[2] = b23.x; rb2[3] = b23.y;
#pragma unroll
            for (int i = 0; i < 8; i++) {
                ull ra2 = pack2(ra[i]);
#pragma unroll
                for (int j = 0; j < 4; j++)
                    fma2(acc2[i][j], ra2, rb2[j]);
            }
        }
        __syncthreads();
    }

#pragma unroll
    for (int i = 0; i < 8; i++) {
        int row = brow + ty * 8 + i;
#pragma unroll
        for (int j2 = 0; j2 < 2; j2++) {
            int col = bcol + tx * 8 + j2 * 4;
            float4 bv = *reinterpret_cast<const float4*>(&bias[col]);
            float2 c0 = unpack2(acc2[i][j2 * 2 + 0]);
            float2 c1 = unpack2(acc2[i][j2 * 2 + 1]);
            float4 cv;
            cv.x = c0.x + bv.x;
            cv.y = c0.y + bv.y;
            cv.z = c1.x + bv.z;
            cv.w = c1.y + bv.w;
            *reinterpret_cast<float4*>(&g_gx[(size_t)row * G3 + col]) = cv;
        }
    }
}

// ---------------------------------------------------------------------------
// Kernel B: persistent GRU recurrence — TPB 256 (NO register spills).
// Cluster of 4 CTAs per 4 batch rows; CTA rank r owns j in [64r, 64r+64).
// GEMM threads: warp kq (8 chunks of 32 k) x lane jp (32 j-pairs).
// Acc: 12 ull = (r,z,n gates) x (4 batches), each = (j0,j1) pair.
// Weights: k-offsets 0..13 in registers (42 ull pairs), 14..31 in smem.
// h stored DUPLICATED (h,h) per batch: GEMM h-operands are broadcast
// LDS.128s, weight operands register/LDS.64 pairs -> zero packs in loop.
// ew phase uses ALL 256 threads; reduction over only 8 partials.
// Sync: st.async + tx-counted ping-pong mbarriers (proven R4/R5 protocol).
// ---------------------------------------------------------------------------
#define TPB_B 256
#define NKREG 14   // k-offsets per chunk held in registers
#define NKSM  18   // k-offsets per chunk held in smem

// smem in ull units: Ws2[8][18][3][32] | hb2[2][256][4] | red[8][4][3][32]
#define ULL_W   0
#define ULL_H   (8 * NKSM * 3 * 32)        // 13824
#define ULL_RED (ULL_H + 2 * 256 * 4)      // 15872
#define ULL_TOT (ULL_RED + 8 * 4 * 3 * 32) // 18944
#define SMEM_B_BYTES (ULL_TOT * 8 + 16)

__device__ __forceinline__ float sigmoidf_fast(float x) {
    return __fdividef(1.0f, 1.0f + __expf(-x));
}
__device__ __forceinline__ float tanhf_fast(float x) {
    x = fminf(fmaxf(x, -15.f), 15.f);
    float e = __expf(2.f * x);
    return __fdividef(e - 1.f, e + 1.f);
}

__device__ __forceinline__ void mbar_wait_parity(uint32_t mbar, uint32_t parity) {
    asm volatile(
        "{\n\t"
        ".reg .pred P;\n\t"
        "WAIT_%=:\n\t"
        "mbarrier.try_wait.parity.acquire.cluster.shared::cta.b64 P, [%0], %1, 0x989680;\n\t"
        "@P bra DONE_%=;\n\t"
        "bra WAIT_%=;\n\t"
        "DONE_%=:\n\t"
        "}"
        :: "r"(mbar), "r"(parity) : "memory");
}

__global__ void __cluster_dims__(4, 1, 1) __launch_bounds__(TPB_B, 1)
gru_rec_kernel(const float* __restrict__ mask,
               const float* __restrict__ Whh,
               const float* __restrict__ bhh,
               float* __restrict__ out)
{
    extern __shared__ ull smu[];
    ull* Ws2 = smu + ULL_W;    // [kq][kk2][g][jp]
    ull* hb2 = smu + ULL_H;    // [2][256 k][4 b] duplicated (h,h)
    ull* red = smu + ULL_RED;  // [kq][b][g][jp]

    const int tid = threadIdx.x;
    uint32_t rank;
    asm("mov.u32 %0, %%cluster_ctarank;" : "=r"(rank));
    const int ci = (int)blockIdx.x >> 2;

    uint32_t sm_u32;
    asm("{ .reg .u64 t; cvta.to.shared.u64 t, %1; cvt.u32.u64 %0, t; }"
        : "=r"(sm_u32) : "l"(smu));
    const uint32_t hb_u32   = sm_u32 + ULL_H * 8;
    const uint32_t mbar_u32 = sm_u32 + ULL_TOT * 8;

    // tx-counted mbarriers: 1 arrival (tid0) + 8192B tx (1024 x 8B) per phase
    if (tid == 0) {
        asm volatile("mbarrier.init.shared.b64 [%0], 1;" :: "r"(mbar_u32) : "memory");
        asm volatile("mbarrier.init.shared.b64 [%0], 1;" :: "r"(mbar_u32 + 8) : "memory");
        asm volatile("mbarrier.arrive.expect_tx.shared.b64 _, [%0], 8192;"
                     :: "r"(mbar_u32) : "memory");
        asm volatile("mbarrier.arrive.expect_tx.shared.b64 _, [%0], 8192;"
                     :: "r"(mbar_u32 + 8) : "memory");
    }

    // Stage smem weights: k-offsets 14..31 of each 32-k chunk
    for (int idx = tid; idx < 8 * NKSM * 3 * 32; idx += TPB_B) {
        int jp_ = idx & 31;
        int g   = (idx >> 5) % 3;
        int kk  = (idx / 96) % NKSM;
        int kq_ = idx / (96 * NKSM);
        int k   = kq_ * 32 + NKREG + kk;
        int base = k * G3 + g * 256 + (int)rank * 64 + jp_ * 2;
        Ws2[idx] = pk(Whh[base], Whh[base + 1]);
    }
    // Zero h buffer (h0 = 0, both parities for safety)
    for (int idx = tid; idx < 2 * 256 * 4; idx += TPB_B) hb2[idx] = 0ull;

    const int kq = tid >> 5;          // warp: k-chunk 0..7
    const int jp = tid & 31;          // lane: j-pair
    const int k0 = kq * 32;
    const int jg0 = (int)rank * 64 + jp * 2;

    // Register weights: k-offsets 0..13, pairs of distinct scalars (no dup)
    ull wr[NKREG], wz[NKREG], wn[NKREG];
#pragma unroll
    for (int kk = 0; kk < NKREG; kk++) {
        int k = k0 + kk;
        wr[kk] = pk(Whh[k * G3 + jg0],       Whh[k * G3 + jg0 + 1]);
        wz[kk] = pk(Whh[k * G3 + 256 + jg0], Whh[k * G3 + 256 + jg0 + 1]);
        wn[kk] = pk(Whh[k * G3 + 512 + jg0], Whh[k * G3 + 512 + jg0 + 1]);
    }

    // Elementwise mapping: ALL 256 threads: j = tid&63, b = tid>>6
    const int je = tid & 63;
    const int be = tid >> 6;
    const int jge = (int)rank * 64 + je;
    const float bhr = bhh[jge];
    const float bhz = bhh[256 + jge];
    const float bhn = bhh[512 + jge];
    const int bbg = ci * 4 + be;
    const float* gx_p = g_gx + (size_t)bbg * Ssz * G3;
    const float* m_p  = mask + (size_t)bbg * Ssz;
    float* out_p = out + (size_t)bbg * Ssz * Hsz + jge;

    __syncthreads();
    asm volatile("barrier.cluster.arrive.aligned;" ::: "memory");
    asm volatile("barrier.cluster.wait.aligned;" ::: "memory");

    int ph0 = 0, ph1 = 0;

    for (int t = 0; t < Ssz; t++) {
        // gx/mask prefetch BEFORE the wait (no h dependency)
        const float* gxt = gx_p + (size_t)t * G3;
        float gxr = __ldcs(gxt + jge);
        float gxz = __ldcs(gxt + 256 + jge);
        float gxn = __ldcs(gxt + 512 + jge);
        float mt  = __ldg(m_p + t);

        const int mi = t & 1;
        if (t > 0) {
            uint32_t mb = mbar_u32 + (uint32_t)(mi * 8);
            if (mi == 0) { mbar_wait_parity(mb, ph0); ph0 ^= 1; }
            else         { mbar_wait_parity(mb, ph1); ph1 ^= 1; }
            if (tid == 0 && t + 2 < Ssz)
                asm volatile("mbarrier.arrive.expect_tx.shared.b64 _, [%0], 8192;"
                             :: "r"(mb) : "memory");
        }

        float hold = reinterpret_cast<const float*>(
            &hb2[mi * 1024 + jge * 4 + be])[0];

        // ---- gh partial GEMM: k in [k0, k0+32), pack-free FFMA2 ----
        ull ar[4] = {0, 0, 0, 0}, az[4] = {0, 0, 0, 0}, an[4] = {0, 0, 0, 0};
        const ull* hK = hb2 + mi * 1024 + k0 * 4;

        // k-offsets 0..13: register weights
#pragma unroll
        for (int kk = 0; kk < NKREG; kk++) {
            ulonglong2 h01 = *reinterpret_cast<const ulonglong2*>(hK + kk * 4);
            ulonglong2 h23 = *reinterpret_cast<const ulonglong2*>(hK + kk * 4 + 2);
            ull hh[4] = {h01.x, h01.y, h23.x, h23.y};
#pragma unroll
            for (int b = 0; b < 4; b++) {
                fma2(ar[b], hh[b], wr[kk]);
                fma2(az[b], hh[b], wz[kk]);
                fma2(an[b], hh[b], wn[kk]);
            }
        }
        // k-offsets 14..31: smem weight pairs (LDS.64)
#pragma unroll
        for (int kk2 = 0; kk2 < NKSM; kk2++) {
            const ull* wb = Ws2 + ((kq * NKSM + kk2) * 3) * 32 + jp;
            ull w_r = wb[0];
            ull w_z = wb[32];
            ull w_n = wb[64];
            int kk = NKREG + kk2;
            ulonglong2 h01 = *reinterpret_cast<const ulonglong2*>(hK + kk * 4);
            ulonglong2 h23 = *reinterpret_cast<const ulonglong2*>(hK + kk * 4 + 2);
            ull hh[4] = {h01.x, h01.y, h23.x, h23.y};
#pragma unroll
            for (int b = 0; b < 4; b++) {
                fma2(ar[b], hh[b], w_r);
                fma2(az[b], hh[b], w_z);
                fma2(an[b], hh[b], w_n);
            }
        }

        // partials -> red[kq][b][g][jp]
        {
            ull* rb = red + kq * 384 + jp;
#pragma unroll
            for (int b = 0; b < 4; b++) {
                rb[b * 96]      = ar[b];
                rb[b * 96 + 32] = az[b];
                rb[b * 96 + 64] = an[b];
            }
        }
        __syncthreads();

        // ---- elementwise gates + h update (ALL 256 threads) ----
        {
            float ghr = bhr, ghz = bhz, ghn = bhn;
            const float* redf = reinterpret_cast<const float*>(red);
            // float index: kq*768 + b*192 + g*64 + j
            const int fb = be * 192 + je;
#pragma unroll
            for (int q = 0; q < 8; q++) {
                const float* rp = redf + q * 768 + fb;
                ghr += rp[0];
                ghz += rp[64];
                ghn += rp[128];
            }
            float r = sigmoidf_fast(gxr + ghr);
            float z = sigmoidf_fast(gxz + ghz);
            float n = tanhf_fast(fmaf(r, ghn, gxn));
            float hnew = fmaf(z, hold - n, n);           // (1-z)*n + z*hold
            float hout = fmaf(mt, hnew - hold, hold);    // m*hnew + (1-m)*hold
            out_p[(size_t)t * Hsz] = hout;

            if (t < Ssz - 1) {
                // async duplicated store into hb2[(t+1)&1] of all 4 CTAs
                ull hd = pk(hout, hout);
                uint32_t laddr = hb_u32 +
                    (uint32_t)(((((t + 1) & 1) * 1024) + jge * 4 + be) * 8);
                uint32_t lmb = mbar_u32 + (uint32_t)(((t + 1) & 1) * 8);
#pragma unroll
                for (int pp = 0; pp < 4; pp++) {
                    uint32_t raddr, rmb;
                    asm volatile("mapa.shared::cluster.u32 %0, %1, %2;"
                                 : "=r"(raddr) : "r"(laddr), "r"(pp));
                    asm volatile("mapa.shared::cluster.u32 %0, %1, %2;"
                                 : "=r"(rmb) : "r"(lmb), "r"(pp));
                    asm volatile(
                        "st.async.shared::cluster.mbarrier::complete_tx::bytes.b64 "
                        "[%0], %1, [%2];"
                        :: "r"(raddr), "l"(hd), "r"(rmb) : "memory");
                }
            }
        }
        __syncthreads();   // red reads done before next step's STS
    }
}

// ---------------------------------------------------------------------------
extern "C" void kernel_launch(void* const* d_in, const int* in_sizes, int n_in,
                              void* d_out, int out_size)
{
    (void)in_sizes; (void)n_in; (void)out_size;
    const float* x    = (const float*)d_in[0];
    const float* mask = (const float*)d_in[1];
    const float* Wih  = (const float*)d_in[2];
    const float* Whh  = (const float*)d_in[3];
    const float* bih  = (const float*)d_in[4];
    const float* bhh  = (const float*)d_in[5];
    float* out = (float*)d_out;

    cudaFuncSetAttribute(gru_rec_kernel,
                         cudaFuncAttributeMaxDynamicSharedMemorySize,
                         SMEM_B_BYTES);

    dim3 gridA(G3 / 128, (Bsz * Ssz) / 128);
    gemm_gx_kernel<<<gridA, 256>>>(x, Wih, bih);

    gru_rec_kernel<<<Bsz, TPB_B, SMEM_B_BYTES>>>(mask, Whh, bhh, out);
}

// round 7
// speedup vs baseline: 1.3358x; 1.2521x over previous
#include <cuda_runtime.h>
#include <cstdint>
#include <cstddef>

#define Bsz 128
#define Ssz 1024
#define Dsz 256
#define Hsz 256
#define G3  768

// 402 MB scratch for precomputed input gates gx = x @ W_ih + b_ih
__device__ float g_gx[(size_t)Bsz * Ssz * G3];

typedef unsigned long long ull;

__device__ __forceinline__ ull pack2(float a) {
    ull r;
    asm("mov.b64 %0, {%1, %1};" : "=l"(r) : "f"(a));
    return r;
}
__device__ __forceinline__ ull pk(float a, float b) {
    ull r;
    asm("mov.b64 %0, {%1, %2};" : "=l"(r) : "f"(a), "f"(b));
    return r;
}
__device__ __forceinline__ void fma2(ull& acc, ull a, ull b) {
    asm("fma.rn.f32x2 %0, %1, %2, %0;" : "+l"(acc) : "l"(a), "l"(b));
}
__device__ __forceinline__ float2 unpack2(ull v) {
    float2 f;
    asm("mov.b64 {%0, %1}, %2;" : "=f"(f.x), "=f"(f.y) : "l"(v));
    return f;
}

// ---------------------------------------------------------------------------
// Kernel A: gx[M=131072, 768] = X[M,256] @ W_ih[256,768] + b_ih
// 128x128 block tile, BK=32, 256 threads, 8x8 microtile FFMA2,
// register-prefetched global loads, 2 CTAs/SM. (unchanged from R6)
// ---------------------------------------------------------------------------
__global__ __launch_bounds__(256, 2) void gemm_gx_kernel(
    const float* __restrict__ X, const float* __restrict__ W,
    const float* __restrict__ bias)
{
    __shared__ float As[32][128];
    __shared__ float Bs[32][128];

    const int tid  = threadIdx.x;
    const int brow = blockIdx.y * 128;
    const int bcol = blockIdx.x * 128;
    const int ty   = tid >> 4;
    const int tx   = tid & 15;

    ull acc2[8][4];
#pragma unroll
    for (int i = 0; i < 8; i++)
#pragma unroll
        for (int j = 0; j < 4; j++) acc2[i][j] = 0ull;

    int aoff[4], akk[4], bkk[4], bcc[4];
#pragma unroll
    for (int it = 0; it < 4; it++) {
        int id = tid + it * 256;
        aoff[it] = id >> 3;
        akk[it]  = (id & 7) << 2;
        bkk[it]  = id >> 5;
        bcc[it]  = (id & 31) << 2;
    }

    float4 pa[4], pb[4];
#pragma unroll
    for (int it = 0; it < 4; it++) {
        pa[it] = *reinterpret_cast<const float4*>(
            &X[(size_t)(brow + aoff[it]) * Dsz + akk[it]]);
        pb[it] = *reinterpret_cast<const float4*>(
            &W[(size_t)bkk[it] * G3 + bcol + bcc[it]]);
    }

    for (int k0 = 0; k0 < Dsz; k0 += 32) {
#pragma unroll
        for (int it = 0; it < 4; it++) {
            As[akk[it] + 0][aoff[it]] = pa[it].x;
            As[akk[it] + 1][aoff[it]] = pa[it].y;
            As[akk[it] + 2][aoff[it]] = pa[it].z;
            As[akk[it] + 3][aoff[it]] = pa[it].w;
            *reinterpret_cast<float4*>(&Bs[bkk[it]][bcc[it]]) = pb[it];
        }
        __syncthreads();

        if (k0 + 32 < Dsz) {
#pragma unroll
            for (int it = 0; it < 4; it++) {
                pa[it] = *reinterpret_cast<const float4*>(
                    &X[(size_t)(brow + aoff[it]) * Dsz + (k0 + 32) + akk[it]]);
                pb[it] = *reinterpret_cast<const float4*>(
                    &W[(size_t)((k0 + 32) + bkk[it]) * G3 + bcol + bcc[it]]);
            }
        }

#pragma unroll 8
        for (int kk = 0; kk < 32; kk++) {
            float ra[8];
            ull   rb2[4];
            *reinterpret_cast<float4*>(&ra[0]) = *reinterpret_cast<float4*>(&As[kk][ty * 8]);
            *reinterpret_cast<float4*>(&ra[4]) = *reinterpret_cast<float4*>(&As[kk][ty * 8 + 4]);
            ulonglong2 b01 = *reinterpret_cast<ulonglong2*>(&Bs[kk][tx * 8]);
            ulonglong2 b23 = *reinterpret_cast<ulonglong2*>(&Bs[kk][tx * 8 + 4]);
            rb2[0] = b01.x; rb2[1] = b01.y; rb2[2] = b23.x; rb2[3] = b23.y;
#pragma unroll
            for (int i = 0; i < 8; i++) {
                ull ra2 = pack2(ra[i]);
#pragma unroll
                for (int j = 0; j < 4; j++)
                    fma2(acc2[i][j], ra2, rb2[j]);
            }
        }
        __syncthreads();
    }

#pragma unroll
    for (int i = 0; i < 8; i++) {
        int row = brow + ty * 8 + i;
#pragma unroll
        for (int j2 = 0; j2 < 2; j2++) {
            int col = bcol + tx * 8 + j2 * 4;
            float4 bv = *reinterpret_cast<const float4*>(&bias[col]);
            float2 c0 = unpack2(acc2[i][j2 * 2 + 0]);
            float2 c1 = unpack2(acc2[i][j2 * 2 + 1]);
            float4 cv;
            cv.x = c0.x + bv.x;
            cv.y = c0.y + bv.y;
            cv.z = c1.x + bv.z;
            cv.w = c1.y + bv.w;
            *reinterpret_cast<float4*>(&g_gx[(size_t)row * G3 + col]) = cv;
        }
    }
}

// ---------------------------------------------------------------------------
// Kernel B: persistent GRU recurrence — BULK DSMEM h exchange.
// Same compute structure as R6 (TPB 256, pack-free FFMA2, reg+smem weights).
// h exchange: ew threads write h pairs to a LOCAL double-buffered staging
// region; after __syncthreads, 4 threads each issue ONE
// cp.async.bulk.shared::cluster.shared::cta (2 KB) to a destination CTA's
// hb2 slot, tx-credited to that CTA's ping-pong mbarrier.
// 1024 scalar DSMEM messages/step -> 4 bulk transfers/step.
// ---------------------------------------------------------------------------
#define TPB_B 256
#define NKREG 14
#define NKSM  18

// smem in ull units:
// Ws2[8][18][3][32] | hb2[2][256][4] | red[8][4][3][32] | stage[2][256]
#define ULL_W     0
#define ULL_H     (8 * NKSM * 3 * 32)          // 13824
#define ULL_RED   (ULL_H + 2 * 256 * 4)        // 15872
#define ULL_STAGE (ULL_RED + 8 * 4 * 3 * 32)   // 18944
#define ULL_TOT   (ULL_STAGE + 2 * 256)        // 19456
#define SMEM_B_BYTES (ULL_TOT * 8 + 16)

__device__ __forceinline__ float sigmoidf_fast(float x) {
    return __fdividef(1.0f, 1.0f + __expf(-x));
}
__device__ __forceinline__ float tanhf_fast(float x) {
    x = fminf(fmaxf(x, -15.f), 15.f);
    float e = __expf(2.f * x);
    return __fdividef(e - 1.f, e + 1.f);
}

__device__ __forceinline__ void mbar_wait_parity(uint32_t mbar, uint32_t parity) {
    asm volatile(
        "{\n\t"
        ".reg .pred P;\n\t"
        "WAIT_%=:\n\t"
        "mbarrier.try_wait.parity.acquire.cluster.shared::cta.b64 P, [%0], %1, 0x989680;\n\t"
        "@P bra DONE_%=;\n\t"
        "bra WAIT_%=;\n\t"
        "DONE_%=:\n\t"
        "}"
        :: "r"(mbar), "r"(parity) : "memory");
}

__global__ void __cluster_dims__(4, 1, 1) __launch_bounds__(TPB_B, 1)
gru_rec_kernel(const float* __restrict__ mask,
               const float* __restrict__ Whh,
               const float* __restrict__ bhh,
               float* __restrict__ out)
{
    extern __shared__ ull smu[];
    ull* Ws2   = smu + ULL_W;     // [kq][kk2][g][jp]
    ull* hb2   = smu + ULL_H;     // [2][256 k][4 b] duplicated (h,h)
    ull* red   = smu + ULL_RED;   // [kq][b][g][jp]
    ull* stage = smu + ULL_STAGE; // [2][64 j][4 b] local h staging

    const int tid = threadIdx.x;
    uint32_t rank;
    asm("mov.u32 %0, %%cluster_ctarank;" : "=r"(rank));
    const int ci = (int)blockIdx.x >> 2;

    uint32_t sm_u32;
    asm("{ .reg .u64 t; cvta.to.shared.u64 t, %1; cvt.u32.u64 %0, t; }"
        : "=r"(sm_u32) : "l"(smu));
    const uint32_t hb_u32    = sm_u32 + ULL_H * 8;
    const uint32_t stage_u32 = sm_u32 + ULL_STAGE * 8;
    const uint32_t mbar_u32  = sm_u32 + ULL_TOT * 8;

    // tx-counted mbarriers: 1 arrival (tid0) + 8192B tx (4 x 2KB) per phase
    if (tid == 0) {
        asm volatile("mbarrier.init.shared.b64 [%0], 1;" :: "r"(mbar_u32) : "memory");
        asm volatile("mbarrier.init.shared.b64 [%0], 1;" :: "r"(mbar_u32 + 8) : "memory");
        asm volatile("mbarrier.arrive.expect_tx.shared.b64 _, [%0], 8192;"
                     :: "r"(mbar_u32) : "memory");
        asm volatile("mbarrier.arrive.expect_tx.shared.b64 _, [%0], 8192;"
                     :: "r"(mbar_u32 + 8) : "memory");
    }

    // Stage smem weights: k-offsets NKREG..31 of each 32-k chunk
    for (int idx = tid; idx < 8 * NKSM * 3 * 32; idx += TPB_B) {
        int jp_ = idx & 31;
        int g   = (idx >> 5) % 3;
        int kk  = (idx / 96) % NKSM;
        int kq_ = idx / (96 * NKSM);
        int k   = kq_ * 32 + NKREG + kk;
        int base = k * G3 + g * 256 + (int)rank * 64 + jp_ * 2;
        Ws2[idx] = pk(Whh[base], Whh[base + 1]);
    }
    for (int idx = tid; idx < 2 * 256 * 4; idx += TPB_B) hb2[idx] = 0ull;

    const int kq = tid >> 5;
    const int jp = tid & 31;
    const int k0 = kq * 32;
    const int jg0 = (int)rank * 64 + jp * 2;

    // Register weights: k-offsets 0..NKREG-1, pairs of distinct scalars
    ull wr[NKREG], wz[NKREG], wn[NKREG];
#pragma unroll
    for (int kk = 0; kk < NKREG; kk++) {
        int k = k0 + kk;
        wr[kk] = pk(Whh[k * G3 + jg0],       Whh[k * G3 + jg0 + 1]);
        wz[kk] = pk(Whh[k * G3 + 256 + jg0], Whh[k * G3 + 256 + jg0 + 1]);
        wn[kk] = pk(Whh[k * G3 + 512 + jg0], Whh[k * G3 + 512 + jg0 + 1]);
    }

    // Elementwise mapping: ALL 256 threads: j = tid&63, b = tid>>6
    const int je = tid & 63;
    const int be = tid >> 6;
    const int jge = (int)rank * 64 + je;
    const float bhr = bhh[jge];
    const float bhz = bhh[256 + jge];
    const float bhn = bhh[512 + jge];
    const int bbg = ci * 4 + be;
    const float* gx_p = g_gx + (size_t)bbg * Ssz * G3;
    const float* m_p  = mask + (size_t)bbg * Ssz;
    float* out_p = out + (size_t)bbg * Ssz * Hsz + jge;

    __syncthreads();
    asm volatile("barrier.cluster.arrive.aligned;" ::: "memory");
    asm volatile("barrier.cluster.wait.aligned;" ::: "memory");

    int ph0 = 0, ph1 = 0;

    for (int t = 0; t < Ssz; t++) {
        // gx/mask prefetch BEFORE the wait (no h dependency)
        const float* gxt = gx_p + (size_t)t * G3;
        float gxr = __ldcs(gxt + jge);
        float gxz = __ldcs(gxt + 256 + jge);
        float gxn = __ldcs(gxt + 512 + jge);
        float mt  = __ldg(m_p + t);

        const int mi = t & 1;
        if (t > 0) {
            uint32_t mb = mbar_u32 + (uint32_t)(mi * 8);
            if (mi == 0) { mbar_wait_parity(mb, ph0); ph0 ^= 1; }
            else         { mbar_wait_parity(mb, ph1); ph1 ^= 1; }
            if (tid == 0 && t + 2 < Ssz)
                asm volatile("mbarrier.arrive.expect_tx.shared.b64 _, [%0], 8192;"
                             :: "r"(mb) : "memory");
        }

        float hold = reinterpret_cast<const float*>(
            &hb2[mi * 1024 + jge * 4 + be])[0];

        // ---- gh partial GEMM: k in [k0, k0+32), pack-free FFMA2 ----
        ull ar[4] = {0, 0, 0, 0}, az[4] = {0, 0, 0, 0}, an[4] = {0, 0, 0, 0};
        const ull* hK = hb2 + mi * 1024 + k0 * 4;

#pragma unroll
        for (int kk = 0; kk < NKREG; kk++) {
            ulonglong2 h01 = *reinterpret_cast<const ulonglong2*>(hK + kk * 4);
            ulonglong2 h23 = *reinterpret_cast<const ulonglong2*>(hK + kk * 4 + 2);
            ull hh[4] = {h01.x, h01.y, h23.x, h23.y};
#pragma unroll
            for (int b = 0; b < 4; b++) {
                fma2(ar[b], hh[b], wr[kk]);
                fma2(az[b], hh[b], wz[kk]);
                fma2(an[b], hh[b], wn[kk]);
            }
        }
#pragma unroll
        for (int kk2 = 0; kk2 < NKSM; kk2++) {
            const ull* wb = Ws2 + ((kq * NKSM + kk2) * 3) * 32 + jp;
            ull w_r = wb[0];
            ull w_z = wb[32];
            ull w_n = wb[64];
            int kk = NKREG + kk2;
            ulonglong2 h01 = *reinterpret_cast<const ulonglong2*>(hK + kk * 4);
            ulonglong2 h23 = *reinterpret_cast<const ulonglong2*>(hK + kk * 4 + 2);
            ull hh[4] = {h01.x, h01.y, h23.x, h23.y};
#pragma unroll
            for (int b = 0; b < 4; b++) {
                fma2(ar[b], hh[b], w_r);
                fma2(az[b], hh[b], w_z);
                fma2(an[b], hh[b], w_n);
            }
        }

        // partials -> red[kq][b][g][jp]
        {
            ull* rb = red + kq * 384 + jp;
#pragma unroll
            for (int b = 0; b < 4; b++) {
                rb[b * 96]      = ar[b];
                rb[b * 96 + 32] = az[b];
                rb[b * 96 + 64] = an[b];
            }
        }
        __syncthreads();

        // ---- elementwise gates + h update (ALL 256 threads) ----
        {
            float ghr = bhr, ghz = bhz, ghn = bhn;
            const float* redf = reinterpret_cast<const float*>(red);
            const int fb = be * 192 + je;   // float idx: kq*768 + b*192 + g*64 + j
#pragma unroll
            for (int q = 0; q < 8; q++) {
                const float* rp = redf + q * 768 + fb;
                ghr += rp[0];
                ghz += rp[64];
                ghn += rp[128];
            }
            float r = sigmoidf_fast(gxr + ghr);
            float z = sigmoidf_fast(gxz + ghz);
            float n = tanhf_fast(fmaf(r, ghn, gxn));
            float hnew = fmaf(z, hold - n, n);           // (1-z)*n + z*hold
            float hout = fmaf(mt, hnew - hold, hold);    // m*hnew + (1-m)*hold
            out_p[(size_t)t * Hsz] = hout;

            // stage h pair locally (double-buffered by step parity)
            stage[(t & 1) * 256 + je * 4 + be] = pk(hout, hout);
        }
        __syncthreads();   // stage + red reads complete

        // ---- bulk DSMEM broadcast: 4 x 2KB copies, tx-credited ----
        if (t < Ssz - 1 && tid < 4) {
            asm volatile("fence.proxy.async.shared::cta;" ::: "memory");
            uint32_t src = stage_u32 + (uint32_t)((t & 1) * 256 * 8);
            // our slice lives at the same offset in every CTA's hb2
            uint32_t dst_local = hb_u32 +
                (uint32_t)((((t + 1) & 1) * 1024 + (int)rank * 256) * 8);
            uint32_t mb_local = mbar_u32 + (uint32_t)(((t + 1) & 1) * 8);
            uint32_t dst_r, mb_r;
            asm volatile("mapa.shared::cluster.u32 %0, %1, %2;"
                         : "=r"(dst_r) : "r"(dst_local), "r"(tid));
            asm volatile("mapa.shared::cluster.u32 %0, %1, %2;"
                         : "=r"(mb_r) : "r"(mb_local), "r"(tid));
            asm volatile(
                "cp.async.bulk.shared::cluster.shared::cta."
                "mbarrier::complete_tx::bytes [%0], [%1], %2, [%3];"
                :: "r"(dst_r), "r"(src), "r"(2048), "r"(mb_r) : "memory");
        }
    }
}

// ---------------------------------------------------------------------------
extern "C" void kernel_launch(void* const* d_in, const int* in_sizes, int n_in,
                              void* d_out, int out_size)
{
    (void)in_sizes; (void)n_in; (void)out_size;
    const float* x    = (const float*)d_in[0];
    const float* mask = (const float*)d_in[1];
    const float* Wih  = (const float*)d_in[2];
    const float* Whh  = (const float*)d_in[3];
    const float* bih  = (const float*)d_in[4];
    const float* bhh  = (const float*)d_in[5];
    float* out = (float*)d_out;

    cudaFuncSetAttribute(gru_rec_kernel,
                         cudaFuncAttributeMaxDynamicSharedMemorySize,
                         SMEM_B_BYTES);

    dim3 gridA(G3 / 128, (Bsz * Ssz) / 128);
    gemm_gx_kernel<<<gridA, 256>>>(x, Wih, bih);

    gru_rec_kernel<<<Bsz, TPB_B, SMEM_B_BYTES>>>(mask, Whh, bhh, out);
}

// round 8
// speedup vs baseline: 1.3755x; 1.0298x over previous
#include <cuda_runtime.h>
#include <cstdint>
#include <cstddef>

#define Bsz 128
#define Ssz 1024
#define Dsz 256
#define Hsz 256
#define G3  768

// 402 MB scratch for precomputed input gates gx = x @ W_ih + b_ih
__device__ float g_gx[(size_t)Bsz * Ssz * G3];

typedef unsigned long long ull;

__device__ __forceinline__ ull pack2(float a) {
    ull r;
    asm("mov.b64 %0, {%1, %1};" : "=l"(r) : "f"(a));
    return r;
}
__device__ __forceinline__ ull pk(float a, float b) {
    ull r;
    asm("mov.b64 %0, {%1, %2};" : "=l"(r) : "f"(a), "f"(b));
    return r;
}
__device__ __forceinline__ void fma2(ull& acc, ull a, ull b) {
    asm("fma.rn.f32x2 %0, %1, %2, %0;" : "+l"(acc) : "l"(a), "l"(b));
}
__device__ __forceinline__ float2 unpack2(ull v) {
    float2 f;
    asm("mov.b64 {%0, %1}, %2;" : "=f"(f.x), "=f"(f.y) : "l"(v));
    return f;
}

// ---------------------------------------------------------------------------
// Kernel A: gx[M=131072, 768] = X[M,256] @ W_ih[256,768] + b_ih
// 128x128 block tile, BK=32, DOUBLE-BUFFERED smem (64KB dynamic),
// ONE __syncthreads per K-tile, 256 threads, 8x8 microtile FFMA2, 2 CTAs/SM.
// ---------------------------------------------------------------------------
#define SMEM_A_BYTES (2 * 8192 * 4)   // 2 buffers x (As 32x128 + Bs 32x128)

__global__ __launch_bounds__(256, 2) void gemm_gx_kernel(
    const float* __restrict__ X, const float* __restrict__ W,
    const float* __restrict__ bias)
{
    extern __shared__ float smA[];
    // buffer p: As = smA + p*8192 (As[k][row]), Bs = As + 4096 (Bs[k][col])

    const int tid  = threadIdx.x;
    const int brow = blockIdx.y * 128;
    const int bcol = blockIdx.x * 128;
    const int ty   = tid >> 4;
    const int tx   = tid & 15;

    ull acc2[8][4];
#pragma unroll
    for (int i = 0; i < 8; i++)
#pragma unroll
        for (int j = 0; j < 4; j++) acc2[i][j] = 0ull;

    int aoff[4], akk[4], bkk[4], bcc[4];
#pragma unroll
    for (int it = 0; it < 4; it++) {
        int id = tid + it * 256;
        aoff[it] = id >> 3;            // A row 0..127
        akk[it]  = (id & 7) << 2;      // A k sub 0..28
        bkk[it]  = id >> 5;            // B k 0..31
        bcc[it]  = (id & 31) << 2;     // B col 0..124
    }

    float4 pa[4], pb[4];
#pragma unroll
    for (int it = 0; it < 4; it++) {
        pa[it] = *reinterpret_cast<const float4*>(
            &X[(size_t)(brow + aoff[it]) * Dsz + akk[it]]);
        pb[it] = *reinterpret_cast<const float4*>(
            &W[(size_t)bkk[it] * G3 + bcol + bcc[it]]);
    }

    // commit tile 0 into buffer 0
    {
        float* As = smA;
        float* Bs = smA + 4096;
#pragma unroll
        for (int it = 0; it < 4; it++) {
            As[(akk[it] + 0) * 128 + aoff[it]] = pa[it].x;
            As[(akk[it] + 1) * 128 + aoff[it]] = pa[it].y;
            As[(akk[it] + 2) * 128 + aoff[it]] = pa[it].z;
            As[(akk[it] + 3) * 128 + aoff[it]] = pa[it].w;
            *reinterpret_cast<float4*>(&Bs[bkk[it] * 128 + bcc[it]]) = pb[it];
        }
    }
    __syncthreads();

    for (int it8 = 0; it8 < 8; it8++) {
        const int p = it8 & 1;
        float* As = smA + p * 8192;
        float* Bs = As + 4096;

        // issue next tile's global loads (hidden under compute below)
        if (it8 < 7) {
            int k0n = (it8 + 1) * 32;
#pragma unroll
            for (int it = 0; it < 4; it++) {
                pa[it] = *reinterpret_cast<const float4*>(
                    &X[(size_t)(brow + aoff[it]) * Dsz + k0n + akk[it]]);
                pb[it] = *reinterpret_cast<const float4*>(
                    &W[(size_t)(k0n + bkk[it]) * G3 + bcol + bcc[it]]);
            }
        }

#pragma unroll 8
        for (int kk = 0; kk < 32; kk++) {
            float ra[8];
            ull   rb2[4];
            *reinterpret_cast<float4*>(&ra[0]) =
                *reinterpret_cast<float4*>(&As[kk * 128 + ty * 8]);
            *reinterpret_cast<float4*>(&ra[4]) =
                *reinterpret_cast<float4*>(&As[kk * 128 + ty * 8 + 4]);
            ulonglong2 b01 = *reinterpret_cast<ulonglong2*>(&Bs[kk * 128 + tx * 8]);
            ulonglong2 b23 = *reinterpret_cast<ulonglong2*>(&Bs[kk * 128 + tx * 8 + 4]);
            rb2[0] = b01.x; rb2[1] = b01.y; rb2[2] = b23.x; rb2[3] = b23.y;
#pragma unroll
            for (int i = 0; i < 8; i++) {
                ull ra2 = pack2(ra[i]);
#pragma unroll
                for (int j = 0; j < 4; j++)
                    fma2(acc2[i][j], ra2, rb2[j]);
            }
        }

        // commit prefetched tile into the OTHER buffer, then single sync
        if (it8 < 7) {
            float* Asn = smA + (p ^ 1) * 8192;
            float* Bsn = Asn + 4096;
#pragma unroll
            for (int it = 0; it < 4; it++) {
                Asn[(akk[it] + 0) * 128 + aoff[it]] = pa[it].x;
                Asn[(akk[it] + 1) * 128 + aoff[it]] = pa[it].y;
                Asn[(akk[it] + 2) * 128 + aoff[it]] = pa[it].z;
                Asn[(akk[it] + 3) * 128 + aoff[it]] = pa[it].w;
                *reinterpret_cast<float4*>(&Bsn[bkk[it] * 128 + bcc[it]]) = pb[it];
            }
            __syncthreads();
        }
    }

#pragma unroll
    for (int i = 0; i < 8; i++) {
        int row = brow + ty * 8 + i;
#pragma unroll
        for (int j2 = 0; j2 < 2; j2++) {
            int col = bcol + tx * 8 + j2 * 4;
            float4 bv = *reinterpret_cast<const float4*>(&bias[col]);
            float2 c0 = unpack2(acc2[i][j2 * 2 + 0]);
            float2 c1 = unpack2(acc2[i][j2 * 2 + 1]);
            float4 cv;
            cv.x = c0.x + bv.x;
            cv.y = c0.y + bv.y;
            cv.z = c1.x + bv.z;
            cv.w = c1.y + bv.w;
            *reinterpret_cast<float4*>(&g_gx[(size_t)row * G3 + col]) = cv;
        }
    }
}

// ---------------------------------------------------------------------------
// Kernel B: persistent GRU recurrence — bulk DSMEM h exchange (R7 WIN
// protocol) + MORE register-resident weights (NKREG 20, smem weights 12).
// ---------------------------------------------------------------------------
#define TPB_B 256
#define NKREG 20
#define NKSM  12

// smem in ull units:
// Ws2[8][12][3][32] | hb2[2][256][4] | red[8][4][3][32] | stage[2][256]
#define ULL_W     0
#define ULL_H     (8 * NKSM * 3 * 32)          // 9216
#define ULL_RED   (ULL_H + 2 * 256 * 4)        // 11264
#define ULL_STAGE (ULL_RED + 8 * 4 * 3 * 32)   // 14336
#define ULL_TOT   (ULL_STAGE + 2 * 256)        // 14848
#define SMEM_B_BYTES (ULL_TOT * 8 + 16)

__device__ __forceinline__ float sigmoidf_fast(float x) {
    return __fdividef(1.0f, 1.0f + __expf(-x));
}
__device__ __forceinline__ float tanhf_fast(float x) {
    x = fminf(fmaxf(x, -15.f), 15.f);
    float e = __expf(2.f * x);
    return __fdividef(e - 1.f, e + 1.f);
}

__device__ __forceinline__ void mbar_wait_parity(uint32_t mbar, uint32_t parity) {
    asm volatile(
        "{\n\t"
        ".reg .pred P;\n\t"
        "WAIT_%=:\n\t"
        "mbarrier.try_wait.parity.acquire.cluster.shared::cta.b64 P, [%0], %1, 0x989680;\n\t"
        "@P bra DONE_%=;\n\t"
        "bra WAIT_%=;\n\t"
        "DONE_%=:\n\t"
        "}"
        :: "r"(mbar), "r"(parity) : "memory");
}

__global__ void __cluster_dims__(4, 1, 1) __launch_bounds__(TPB_B, 1)
gru_rec_kernel(const float* __restrict__ mask,
               const float* __restrict__ Whh,
               const float* __restrict__ bhh,
               float* __restrict__ out)
{
    extern __shared__ ull smu[];
    ull* Ws2   = smu + ULL_W;     // [kq][kk2][g][jp]
    ull* hb2   = smu + ULL_H;     // [2][256 k][4 b] duplicated (h,h)
    ull* red   = smu + ULL_RED;   // [kq][b][g][jp]
    ull* stage = smu + ULL_STAGE; // [2][64 j][4 b] local h staging

    const int tid = threadIdx.x;
    uint32_t rank;
    asm("mov.u32 %0, %%cluster_ctarank;" : "=r"(rank));
    const int ci = (int)blockIdx.x >> 2;

    uint32_t sm_u32;
    asm("{ .reg .u64 t; cvta.to.shared.u64 t, %1; cvt.u32.u64 %0, t; }"
        : "=r"(sm_u32) : "l"(smu));
    const uint32_t hb_u32    = sm_u32 + ULL_H * 8;
    const uint32_t stage_u32 = sm_u32 + ULL_STAGE * 8;
    const uint32_t mbar_u32  = sm_u32 + ULL_TOT * 8;

    // tx-counted mbarriers: 1 arrival (tid0) + 8192B tx (4 x 2KB) per phase
    if (tid == 0) {
        asm volatile("mbarrier.init.shared.b64 [%0], 1;" :: "r"(mbar_u32) : "memory");
        asm volatile("mbarrier.init.shared.b64 [%0], 1;" :: "r"(mbar_u32 + 8) : "memory");
        asm volatile("mbarrier.arrive.expect_tx.shared.b64 _, [%0], 8192;"
                     :: "r"(mbar_u32) : "memory");
        asm volatile("mbarrier.arrive.expect_tx.shared.b64 _, [%0], 8192;"
                     :: "r"(mbar_u32 + 8) : "memory");
    }

    // Stage smem weights: k-offsets NKREG..31 of each 32-k chunk
    for (int idx = tid; idx < 8 * NKSM * 3 * 32; idx += TPB_B) {
        int jp_ = idx & 31;
        int g   = (idx >> 5) % 3;
        int kk  = (idx / 96) % NKSM;
        int kq_ = idx / (96 * NKSM);
        int k   = kq_ * 32 + NKREG + kk;
        int base = k * G3 + g * 256 + (int)rank * 64 + jp_ * 2;
        Ws2[idx] = pk(Whh[base], Whh[base + 1]);
    }
    for (int idx = tid; idx < 2 * 256 * 4; idx += TPB_B) hb2[idx] = 0ull;

    const int kq = tid >> 5;
    const int jp = tid & 31;
    const int k0 = kq * 32;
    const int jg0 = (int)rank * 64 + jp * 2;

    // Register weights: k-offsets 0..NKREG-1, pairs of distinct scalars
    ull wr[NKREG], wz[NKREG], wn[NKREG];
#pragma unroll
    for (int kk = 0; kk < NKREG; kk++) {
        int k = k0 + kk;
        wr[kk] = pk(Whh[k * G3 + jg0],       Whh[k * G3 + jg0 + 1]);
        wz[kk] = pk(Whh[k * G3 + 256 + jg0], Whh[k * G3 + 256 + jg0 + 1]);
        wn[kk] = pk(Whh[k * G3 + 512 + jg0], Whh[k * G3 + 512 + jg0 + 1]);
    }

    // Elementwise mapping: ALL 256 threads: j = tid&63, b = tid>>6
    const int je = tid & 63;
    const int be = tid >> 6;
    const int jge = (int)rank * 64 + je;
    const float bhr = bhh[jge];
    const float bhz = bhh[256 + jge];
    const float bhn = bhh[512 + jge];
    const int bbg = ci * 4 + be;
    const float* gx_p = g_gx + (size_t)bbg * Ssz * G3;
    const float* m_p  = mask + (size_t)bbg * Ssz;
    float* out_p = out + (size_t)bbg * Ssz * Hsz + jge;

    __syncthreads();
    asm volatile("barrier.cluster.arrive.aligned;" ::: "memory");
    asm volatile("barrier.cluster.wait.aligned;" ::: "memory");

    int ph0 = 0, ph1 = 0;

    for (int t = 0; t < Ssz; t++) {
        // gx/mask prefetch BEFORE the wait (no h dependency)
        const float* gxt = gx_p + (size_t)t * G3;
        float gxr = __ldcs(gxt + jge);
        float gxz = __ldcs(gxt + 256 + jge);
        float gxn = __ldcs(gxt + 512 + jge);
        float mt  = __ldg(m_p + t);

        const int mi = t & 1;
        if (t > 0) {
            uint32_t mb = mbar_u32 + (uint32_t)(mi * 8);
            if (mi == 0) { mbar_wait_parity(mb, ph0); ph0 ^= 1; }
            else         { mbar_wait_parity(mb, ph1); ph1 ^= 1; }
            if (tid == 0 && t + 2 < Ssz)
                asm volatile("mbarrier.arrive.expect_tx.shared.b64 _, [%0], 8192;"
                             :: "r"(mb) : "memory");
        }

        float hold = reinterpret_cast<const float*>(
            &hb2[mi * 1024 + jge * 4 + be])[0];

        // ---- gh partial GEMM: k in [k0, k0+32), pack-free FFMA2 ----
        ull ar[4] = {0, 0, 0, 0}, az[4] = {0, 0, 0, 0}, an[4] = {0, 0, 0, 0};
        const ull* hK = hb2 + mi * 1024 + k0 * 4;

#pragma unroll
        for (int kk = 0; kk < NKREG; kk++) {
            ulonglong2 h01 = *reinterpret_cast<const ulonglong2*>(hK + kk * 4);
            ulonglong2 h23 = *reinterpret_cast<const ulonglong2*>(hK + kk * 4 + 2);
            ull hh[4] = {h01.x, h01.y, h23.x, h23.y};
#pragma unroll
            for (int b = 0; b < 4; b++) {
                fma2(ar[b], hh[b], wr[kk]);
                fma2(az[b], hh[b], wz[kk]);
                fma2(an[b], hh[b], wn[kk]);
            }
        }
#pragma unroll
        for (int kk2 = 0; kk2 < NKSM; kk2++) {
            const ull* wb = Ws2 + ((kq * NKSM + kk2) * 3) * 32 + jp;
            ull w_r = wb[0];
            ull w_z = wb[32];
            ull w_n = wb[64];
            int kk = NKREG + kk2;
            ulonglong2 h01 = *reinterpret_cast<const ulonglong2*>(hK + kk * 4);
            ulonglong2 h23 = *reinterpret_cast<const ulonglong2*>(hK + kk * 4 + 2);
            ull hh[4] = {h01.x, h01.y, h23.x, h23.y};
#pragma unroll
            for (int b = 0; b < 4; b++) {
                fma2(ar[b], hh[b], w_r);
                fma2(az[b], hh[b], w_z);
                fma2(an[b], hh[b], w_n);
            }
        }

        // partials -> red[kq][b][g][jp]
        {
            ull* rb = red + kq * 384 + jp;
#pragma unroll
            for (int b = 0; b < 4; b++) {
                rb[b * 96]      = ar[b];
                rb[b * 96 + 32] = az[b];
                rb[b * 96 + 64] = an[b];
            }
        }
        __syncthreads();

        // ---- elementwise gates + h update (ALL 256 threads) ----
        {
            float ghr = bhr, ghz = bhz, ghn = bhn;
            const float* redf = reinterpret_cast<const float*>(red);
            const int fb = be * 192 + je;   // float idx: kq*768 + b*192 + g*64 + j
#pragma unroll
            for (int q = 0; q < 8; q++) {
                const float* rp = redf + q * 768 + fb;
                ghr += rp[0];
                ghz += rp[64];
                ghn += rp[128];
            }
            float r = sigmoidf_fast(gxr + ghr);
            float z = sigmoidf_fast(gxz + ghz);
            float n = tanhf_fast(fmaf(r, ghn, gxn));
            float hnew = fmaf(z, hold - n, n);           // (1-z)*n + z*hold
            float hout = fmaf(mt, hnew - hold, hold);    // m*hnew + (1-m)*hold
            out_p[(size_t)t * Hsz] = hout;

            // stage h pair locally (double-buffered by step parity)
            stage[(t & 1) * 256 + je * 4 + be] = pk(hout, hout);
        }
        __syncthreads();   // stage + red reads complete

        // ---- bulk DSMEM broadcast: 4 x 2KB copies, tx-credited ----
        if (t < Ssz - 1 && tid < 4) {
            asm volatile("fence.proxy.async.shared::cta;" ::: "memory");
            uint32_t src = stage_u32 + (uint32_t)((t & 1) * 256 * 8);
            uint32_t dst_local = hb_u32 +
                (uint32_t)((((t + 1) & 1) * 1024 + (int)rank * 256) * 8);
            uint32_t mb_local = mbar_u32 + (uint32_t)(((t + 1) & 1) * 8);
            uint32_t dst_r, mb_r;
            asm volatile("mapa.shared::cluster.u32 %0, %1, %2;"
                         : "=r"(dst_r) : "r"(dst_local), "r"(tid));
            asm volatile("mapa.shared::cluster.u32 %0, %1, %2;"
                         : "=r"(mb_r) : "r"(mb_local), "r"(tid));
            asm volatile(
                "cp.async.bulk.shared::cluster.shared::cta."
                "mbarrier::complete_tx::bytes [%0], [%1], %2, [%3];"
                :: "r"(dst_r), "r"(src), "r"(2048), "r"(mb_r) : "memory");
        }
    }
}

// ---------------------------------------------------------------------------
extern "C" void kernel_launch(void* const* d_in, const int* in_sizes, int n_in,
                              void* d_out, int out_size)
{
    (void)in_sizes; (void)n_in; (void)out_size;
    const float* x    = (const float*)d_in[0];
    const float* mask = (const float*)d_in[1];
    const float* Wih  = (const float*)d_in[2];
    const float* Whh  = (const float*)d_in[3];
    const float* bih  = (const float*)d_in[4];
    const float* bhh  = (const float*)d_in[5];
    float* out = (float*)d_out;

    cudaFuncSetAttribute(gemm_gx_kernel,
                         cudaFuncAttributeMaxDynamicSharedMemorySize,
                         SMEM_A_BYTES);
    cudaFuncSetAttribute(gru_rec_kernel,
                         cudaFuncAttributeMaxDynamicSharedMemorySize,
                         SMEM_B_BYTES);

    dim3 gridA(G3 / 128, (Bsz * Ssz) / 128);
    gemm_gx_kernel<<<gridA, 256, SMEM_A_BYTES>>>(x, Wih, bih);

    gru_rec_kernel<<<Bsz, TPB_B, SMEM_B_BYTES>>>(mask, Whh, bhh, out);
}